// round 9
// baseline (speedup 1.0000x reference)
#include <cuda_runtime.h>
#include <cstdint>

#define BSZ 2048
#define LSZ 512
#define DSZ 128
#define TILE 16          // rows per pipeline stage (8KB K + 8KB V)
#define NST  3           // pipeline depth
#define TILEB (TILE * DSZ * 4)

__device__ int g_len[BSZ];     // normalized lengths (dtype auto-detected)
__device__ int g_perm[BSZ];    // batch rows sorted by descending length

#define WARP_RED_SUM(p)                                   \
    p += __shfl_xor_sync(0xffffffffu, p, 16);             \
    p += __shfl_xor_sync(0xffffffffu, p, 8);              \
    p += __shfl_xor_sync(0xffffffffu, p, 4);              \
    p += __shfl_xor_sync(0xffffffffu, p, 2);              \
    p += __shfl_xor_sync(0xffffffffu, p, 1);

#define WARP_RED_SUM2(a, b)                               \
    a += __shfl_xor_sync(0xffffffffu, a, 16);             \
    b += __shfl_xor_sync(0xffffffffu, b, 16);             \
    a += __shfl_xor_sync(0xffffffffu, a, 8);              \
    b += __shfl_xor_sync(0xffffffffu, b, 8);              \
    a += __shfl_xor_sync(0xffffffffu, a, 4);              \
    b += __shfl_xor_sync(0xffffffffu, b, 4);              \
    a += __shfl_xor_sync(0xffffffffu, a, 2);              \
    b += __shfl_xor_sync(0xffffffffu, b, 2);              \
    a += __shfl_xor_sync(0xffffffffu, a, 1);              \
    b += __shfl_xor_sync(0xffffffffu, b, 1);

#define WARP_RED_SUM4(a, b, c, d)                         \
    WARP_RED_SUM2(a, b)                                   \
    WARP_RED_SUM2(c, d)

__device__ __forceinline__ float dot128(float4 a, float4 b) {
    return fmaf(a.x, b.x, fmaf(a.y, b.y, fmaf(a.z, b.z, a.w * b.w)));
}

// Online softmax update of (m, l, o) with score p and value row v.
#define ONLINE_UPDATE(p, v)                               \
    {                                                     \
        float mn = fmaxf(m, p);                           \
        float cc = __expf(m - mn);                        \
        float ee = __expf(p - mn);                        \
        l = fmaf(l, cc, ee);                              \
        o.x = fmaf(o.x, cc, ee * (v).x);                  \
        o.y = fmaf(o.y, cc, ee * (v).y);                  \
        o.z = fmaf(o.z, cc, ee * (v).z);                  \
        o.w = fmaf(o.w, cc, ee * (v).w);                  \
        m = mn;                                           \
    }

// ---- bulk-async (UBLKCP) + mbarrier primitives --------------------------
__device__ __forceinline__ void mbar_init(uint32_t mbar, uint32_t count) {
    asm volatile("mbarrier.init.shared.b64 [%0], %1;" :: "r"(mbar), "r"(count) : "memory");
}
__device__ __forceinline__ void mbar_expect_tx(uint32_t mbar, uint32_t tx) {
    asm volatile("mbarrier.arrive.expect_tx.shared.b64 _, [%0], %1;"
                 :: "r"(mbar), "r"(tx) : "memory");
}
__device__ __forceinline__ void mbar_arrive(uint32_t mbar) {
    asm volatile("mbarrier.arrive.release.cta.shared::cta.b64 _, [%0];"
                 :: "r"(mbar) : "memory");
}
__device__ __forceinline__ void bulk_g2s(uint32_t dst, const void* src,
                                         uint32_t bytes, uint32_t mbar) {
    asm volatile("cp.async.bulk.shared::cta.global.mbarrier::complete_tx::bytes "
                 "[%0], [%1], %2, [%3];"
                 :: "r"(dst), "l"(src), "r"(bytes), "r"(mbar) : "memory");
}
__device__ __forceinline__ void mbar_wait(uint32_t mbar, uint32_t parity) {
    uint32_t done;
    do {
        asm volatile(
            "{\n\t.reg .pred p;\n\t"
            "mbarrier.try_wait.parity.acquire.cta.shared::cta.b64 p, [%1], %2, 0x989680;\n\t"
            "selp.b32 %0, 1, 0, p;\n\t}"
            : "=r"(done) : "r"(mbar), "r"(parity) : "memory");
    } while (!done);
}
#define CONS_BAR() asm volatile("bar.sync 1, 256;" ::: "memory")

// ---------------------------------------------------------------------------
// Setup: (a) normalize `lengths` to int32 with int32/int64 auto-detect
// (int64 values < 512 have all-zero odd int32 words), (b) counting-sort rows
// by DESCENDING length into g_perm. Parallel shfl-based block scan.
// ---------------------------------------------------------------------------
__global__ __launch_bounds__(1024) void setup_kernel(const int* __restrict__ Lraw) {
    __shared__ int cnt[LSZ];
    __shared__ int wsum[16];
    __shared__ int s_any;
    int tid  = threadIdx.x;                 // single block, 1024 threads
    int lane = tid & 31;
    if (tid == 0) s_any = 0;
    if (tid < LSZ) cnt[tid] = 0;
    __syncthreads();
    if (Lraw[2 * tid + 1] != 0) s_any = 1;  // benign race
    __syncthreads();
    int l0, l1;
    if (s_any == 0) {                       // int64 layout
        const long long* L64 = (const long long*)Lraw;
        l0 = (int)L64[2 * tid];
        l1 = (int)L64[2 * tid + 1];
    } else {                                // int32 layout
        l0 = Lraw[2 * tid];
        l1 = Lraw[2 * tid + 1];
    }
    g_len[2 * tid]     = l0;
    g_len[2 * tid + 1] = l1;
    atomicAdd(&cnt[l0], 1);
    atomicAdd(&cnt[l1], 1);
    __syncthreads();

    int val = 0, incl = 0;
    if (tid < LSZ) {                        // descending exclusive scan
        val  = cnt[LSZ - 1 - tid];
        incl = val;
        #pragma unroll
        for (int d = 1; d < 32; d <<= 1) {
            int t = __shfl_up_sync(0xffffffffu, incl, d);
            if (lane >= d) incl += t;
        }
        if (lane == 31) wsum[tid >> 5] = incl;
    }
    __syncthreads();
    if (tid < 16) {
        int w = wsum[tid];
        int wi = w;
        #pragma unroll
        for (int d = 1; d < 16; d <<= 1) {
            int t = __shfl_up_sync(0x0000ffffu, wi, d);
            if (tid >= d) wi += t;
        }
        wsum[tid] = wi - w;
    }
    __syncthreads();
    if (tid < LSZ) cnt[LSZ - 1 - tid] = (incl - val) + wsum[tid >> 5];
    __syncthreads();

    int p0 = atomicAdd(&cnt[l0], 1); g_perm[p0] = 2 * tid;
    int p1 = atomicAdd(&cnt[l1], 1); g_perm[p1] = 2 * tid + 1;
}

// ---------------------------------------------------------------------------
// Warp-specialized fused kernel. 9 warps: warps 0-7 consume (projection +
// online-softmax attention), warp 8 lane 0 is a free-running TMA producer
// feeding a 3-stage K/V ring with full(tx)/empty(8-arrival) mbarrier pairs.
// No __syncthreads in the streaming loop; consumer-only named barrier.
// ---------------------------------------------------------------------------
__global__ __launch_bounds__(288, 4) void attn_kernel(
    const float* __restrict__ x,
    const float* __restrict__ K, const float* __restrict__ V,
    const float* __restrict__ Wq, const float* __restrict__ bq,
    const float* __restrict__ Wk, const float* __restrict__ bk,
    const float* __restrict__ Wv, const float* __restrict__ bv,
    float* __restrict__ out)
{
    __shared__ __align__(1024) float kbuf[NST][TILE][DSZ];   // 24KB
    __shared__ __align__(1024) float vbuf[NST][TILE][DSZ];   // 24KB
    __shared__ __align__(16) float xs[DSZ];
    __shared__ __align__(16) float qs[DSZ];
    __shared__ __align__(16) float ks[DSZ];
    __shared__ __align__(16) float vs[DSZ];
    __shared__ __align__(16) float s_part[8][DSZ];
    __shared__ float red_m[8];
    __shared__ float red_l[8];
    __shared__ __align__(8) unsigned long long mbar_full[NST];
    __shared__ __align__(8) unsigned long long mbar_empty[NST];

    int tid  = threadIdx.x;
    int lane = tid & 31;
    int wid  = tid >> 5;                // 0-7 consumers, 8 producer
    int b    = g_perm[blockIdx.x];
    int len  = g_len[b];                // 0 .. 511
    int j0   = LSZ - len;
    const float inv_sqrt_d = 0.08838834764831845f;   // 1/sqrt(128)

    size_t base = (size_t)b * LSZ * DSZ;
    const float* Ksuf = K + base + (size_t)j0 * DSZ;    // contiguous len*512B
    const float* Vsuf = V + base + (size_t)j0 * DSZ;
    int ntiles = (len + TILE - 1) / TILE;

    uint32_t fmb0 = (uint32_t)__cvta_generic_to_shared(&mbar_full[0]);
    uint32_t emb0 = (uint32_t)__cvta_generic_to_shared(&mbar_empty[0]);
    uint32_t kb0  = (uint32_t)__cvta_generic_to_shared(&kbuf[0][0][0]);
    uint32_t vb0  = (uint32_t)__cvta_generic_to_shared(&vbuf[0][0][0]);

    if (tid == 0) {
        #pragma unroll
        for (int s = 0; s < NST; ++s) {
            mbar_init(fmb0 + 8 * s, 1);     // tx-based completion
            mbar_init(emb0 + 8 * s, 8);     // 8 consumer-warp arrivals
        }
        asm volatile("fence.proxy.async.shared::cta;" ::: "memory");
    }
    if (tid < 32) ((float4*)xs)[tid] = ((const float4*)(x + (size_t)b * DSZ))[tid];
    __syncthreads();                        // ONLY all-thread barrier

    // ================= PRODUCER (warp 8, lane 0) =================
    if (wid == 8) {
        if (lane == 0) {
            int s = 0;
            for (int t = 0; t < ntiles; ++t) {
                if (t >= NST) {             // stage reused: wait consumers done
                    int ep = ((t - NST) / NST) & 1;
                    mbar_wait(emb0 + 8 * s, ep);
                }
                int rows = min(TILE, len - t * TILE);
                uint32_t bytes = (uint32_t)rows * DSZ * 4;
                mbar_expect_tx(fmb0 + 8 * s, 2 * bytes);
                bulk_g2s(kb0 + s * TILEB, Ksuf + (size_t)t * TILE * DSZ,
                         bytes, fmb0 + 8 * s);
                bulk_g2s(vb0 + s * TILEB, Vsuf + (size_t)t * TILE * DSZ,
                         bytes, fmb0 + 8 * s);
                if (++s == NST) s = 0;
            }
        }
        return;                             // producer exits; no more barriers
    }

    // ================= CONSUMERS (warps 0-7) =================
    // ---- Projection: q[d] = dot(Wq[d,:], x) + bq[d] (same for k,v).
    {
        float4 xv = ((const float4*)xs)[lane];
        #pragma unroll
        for (int mm = 0; mm < 3; ++mm) {
            const float* W    = (mm == 0) ? Wq : ((mm == 1) ? Wk : Wv);
            const float* bias = (mm == 0) ? bq : ((mm == 1) ? bk : bv);
            float* dst        = (mm == 0) ? qs : ((mm == 1) ? ks : vs);
            #pragma unroll
            for (int j = 0; j < 4; ++j) {
                int d0 = wid + 32 * j;
                float4 w0 = ((const float4*)(W + (d0     ) * DSZ))[lane];
                float4 w1 = ((const float4*)(W + (d0 +  8) * DSZ))[lane];
                float4 w2 = ((const float4*)(W + (d0 + 16) * DSZ))[lane];
                float4 w3 = ((const float4*)(W + (d0 + 24) * DSZ))[lane];
                float p0 = dot128(w0, xv);
                float p1 = dot128(w1, xv);
                float p2 = dot128(w2, xv);
                float p3 = dot128(w3, xv);
                WARP_RED_SUM4(p0, p1, p2, p3);
                if (lane == 0) {
                    dst[d0]      = p0 + bias[d0];
                    dst[d0 +  8] = p1 + bias[d0 + 8];
                    dst[d0 + 16] = p2 + bias[d0 + 16];
                    dst[d0 + 24] = p3 + bias[d0 + 24];
                }
            }
        }
    }
    CONS_BAR();

    // ---- Online-softmax stream over pipeline tiles (no block barriers).
    float4 qv = ((const float4*)qs)[lane];
    float  m  = -3.4e38f;
    float  l  = 0.0f;
    float4 o  = make_float4(0.f, 0.f, 0.f, 0.f);

    if (wid == (len & 7)) {              // new pushed entry (order irrelevant)
        float4 kn = ((const float4*)ks)[lane];
        float4 vn = ((const float4*)vs)[lane];
        float p = dot128(kn, qv);
        WARP_RED_SUM(p);
        p *= inv_sqrt_d;
        m = p; l = 1.0f;
        o = vn;
    }

    int cs = 0, cph = 0;
    for (int t = 0; t < ntiles; ++t) {
        mbar_wait(fmb0 + 8 * cs, cph);
        int rows = min(TILE, len - t * TILE);
        bool r0v = wid < rows;
        bool r1v = wid + 8 < rows;
        float4 k0, v0, k1, v1;
        float p0 = 0.0f, p1 = 0.0f;
        if (r0v) {
            k0 = *(const float4*)&kbuf[cs][wid][lane * 4];
            v0 = *(const float4*)&vbuf[cs][wid][lane * 4];
            p0 = dot128(k0, qv);
        }
        if (r1v) {
            k1 = *(const float4*)&kbuf[cs][wid + 8][lane * 4];
            v1 = *(const float4*)&vbuf[cs][wid + 8][lane * 4];
            p1 = dot128(k1, qv);
        }
        WARP_RED_SUM2(p0, p1);
        if (r0v) { p0 *= inv_sqrt_d; ONLINE_UPDATE(p0, v0); }
        if (r1v) { p1 *= inv_sqrt_d; ONLINE_UPDATE(p1, v1); }
        __syncwarp();                    // all lanes consumed the stage
        if (lane == 0) mbar_arrive(emb0 + 8 * cs);
        if (++cs == NST) { cs = 0; cph ^= 1; }
    }

    // ---- Merge the 8 per-warp (m, l, o) triples.
    if (lane == 0) red_m[wid] = m;
    CONS_BAR();
    float M = red_m[0];
    #pragma unroll
    for (int w = 1; w < 8; ++w) M = fmaxf(M, red_m[w]);
    float f = __expf(m - M);             // 0 for warps that saw no rows
    if (lane == 0) red_l[wid] = l * f;
    o.x *= f; o.y *= f; o.z *= f; o.w *= f;
    ((float4*)&s_part[wid][0])[lane] = o;
    CONS_BAR();

    if (tid < DSZ) {
        float L = red_l[0];
        #pragma unroll
        for (int w = 1; w < 8; ++w) L += red_l[w];
        float sm = 0.0f;
        #pragma unroll
        for (int w = 0; w < 8; ++w) sm += s_part[w][tid];
        out[(size_t)b * DSZ + tid] = sm / L;
    }
}

// ---------------------------------------------------------------------------
extern "C" void kernel_launch(void* const* d_in, const int* in_sizes, int n_in,
                              void* d_out, int out_size) {
    const float* inputs      = (const float*)d_in[0];
    const float* prev_keys   = (const float*)d_in[1];
    const float* prev_values = (const float*)d_in[2];
    const float* Wq          = (const float*)d_in[3];
    const float* bq          = (const float*)d_in[4];
    const float* Wk          = (const float*)d_in[5];
    const float* bk          = (const float*)d_in[6];
    const float* Wv          = (const float*)d_in[7];
    const float* bv          = (const float*)d_in[8];
    const int*   lengths_raw = (const int*)d_in[9];
    float* out               = (float*)d_out;

    setup_kernel<<<1, 1024>>>(lengths_raw);
    attn_kernel<<<BSZ, 288>>>(inputs, prev_keys, prev_values,
                              Wq, bq, Wk, bk, Wv, bv, out);
}

// round 10
// speedup vs baseline: 1.0301x; 1.0301x over previous
#include <cuda_runtime.h>
#include <cstdint>

#define BSZ 2048
#define LSZ 512
#define DSZ 128
#define TILE 8           // rows per pipeline stage (4KB K + 4KB V)
#define NST  4           // pipeline depth
#define TILEB (TILE * DSZ * 4)

__device__ int g_len[BSZ];     // normalized lengths (dtype auto-detected)
__device__ int g_perm[BSZ];    // batch rows sorted by descending length

#define WARP_RED_SUM(p)                                   \
    p += __shfl_xor_sync(0xffffffffu, p, 16);             \
    p += __shfl_xor_sync(0xffffffffu, p, 8);              \
    p += __shfl_xor_sync(0xffffffffu, p, 4);              \
    p += __shfl_xor_sync(0xffffffffu, p, 2);              \
    p += __shfl_xor_sync(0xffffffffu, p, 1);

#define WARP_RED_SUM2(a, b)                               \
    a += __shfl_xor_sync(0xffffffffu, a, 16);             \
    b += __shfl_xor_sync(0xffffffffu, b, 16);             \
    a += __shfl_xor_sync(0xffffffffu, a, 8);              \
    b += __shfl_xor_sync(0xffffffffu, b, 8);              \
    a += __shfl_xor_sync(0xffffffffu, a, 4);              \
    b += __shfl_xor_sync(0xffffffffu, b, 4);              \
    a += __shfl_xor_sync(0xffffffffu, a, 2);              \
    b += __shfl_xor_sync(0xffffffffu, b, 2);              \
    a += __shfl_xor_sync(0xffffffffu, a, 1);              \
    b += __shfl_xor_sync(0xffffffffu, b, 1);

#define WARP_RED_SUM4(a, b, c, d)                         \
    WARP_RED_SUM2(a, b)                                   \
    WARP_RED_SUM2(c, d)

__device__ __forceinline__ float dot128(float4 a, float4 b) {
    return fmaf(a.x, b.x, fmaf(a.y, b.y, fmaf(a.z, b.z, a.w * b.w)));
}

// Online softmax update of (m, l, o) with score p and value row v.
#define ONLINE_UPDATE(p, v)                               \
    {                                                     \
        float mn = fmaxf(m, p);                           \
        float cc = __expf(m - mn);                        \
        float ee = __expf(p - mn);                        \
        l = fmaf(l, cc, ee);                              \
        o.x = fmaf(o.x, cc, ee * (v).x);                  \
        o.y = fmaf(o.y, cc, ee * (v).y);                  \
        o.z = fmaf(o.z, cc, ee * (v).z);                  \
        o.w = fmaf(o.w, cc, ee * (v).w);                  \
        m = mn;                                           \
    }

// ---- bulk-async (UBLKCP) + mbarrier primitives --------------------------
__device__ __forceinline__ void mbar_init(uint32_t mbar, uint32_t count) {
    asm volatile("mbarrier.init.shared.b64 [%0], %1;" :: "r"(mbar), "r"(count) : "memory");
}
__device__ __forceinline__ void mbar_expect_tx(uint32_t mbar, uint32_t tx) {
    asm volatile("mbarrier.arrive.expect_tx.shared.b64 _, [%0], %1;"
                 :: "r"(mbar), "r"(tx) : "memory");
}
__device__ __forceinline__ void bulk_g2s(uint32_t dst, const void* src,
                                         uint32_t bytes, uint32_t mbar) {
    asm volatile("cp.async.bulk.shared::cta.global.mbarrier::complete_tx::bytes "
                 "[%0], [%1], %2, [%3];"
                 :: "r"(dst), "l"(src), "r"(bytes), "r"(mbar) : "memory");
}
__device__ __forceinline__ void mbar_wait(uint32_t mbar, uint32_t parity) {
    uint32_t done;
    do {
        asm volatile(
            "{\n\t.reg .pred p;\n\t"
            "mbarrier.try_wait.parity.acquire.cta.shared::cta.b64 p, [%1], %2, 0x989680;\n\t"
            "selp.b32 %0, 1, 0, p;\n\t}"
            : "=r"(done) : "r"(mbar), "r"(parity) : "memory");
    } while (!done);
}

// ---------------------------------------------------------------------------
// Setup: (a) normalize `lengths` to int32 with int32/int64 auto-detect
// (int64 values < 512 have all-zero odd int32 words), (b) counting-sort rows
// by DESCENDING length into g_perm. Parallel shfl-based block scan.
// ---------------------------------------------------------------------------
__global__ __launch_bounds__(1024) void setup_kernel(const int* __restrict__ Lraw) {
    __shared__ int cnt[LSZ];
    __shared__ int wsum[16];
    __shared__ int s_any;
    int tid  = threadIdx.x;                 // single block, 1024 threads
    int lane = tid & 31;
    if (tid == 0) s_any = 0;
    if (tid < LSZ) cnt[tid] = 0;
    __syncthreads();
    if (Lraw[2 * tid + 1] != 0) s_any = 1;  // benign race
    __syncthreads();
    int l0, l1;
    if (s_any == 0) {                       // int64 layout
        const long long* L64 = (const long long*)Lraw;
        l0 = (int)L64[2 * tid];
        l1 = (int)L64[2 * tid + 1];
    } else {                                // int32 layout
        l0 = Lraw[2 * tid];
        l1 = Lraw[2 * tid + 1];
    }
    g_len[2 * tid]     = l0;
    g_len[2 * tid + 1] = l1;
    atomicAdd(&cnt[l0], 1);
    atomicAdd(&cnt[l1], 1);
    __syncthreads();

    int val = 0, incl = 0;
    if (tid < LSZ) {                        // descending exclusive scan
        val  = cnt[LSZ - 1 - tid];
        incl = val;
        #pragma unroll
        for (int d = 1; d < 32; d <<= 1) {
            int t = __shfl_up_sync(0xffffffffu, incl, d);
            if (lane >= d) incl += t;
        }
        if (lane == 31) wsum[tid >> 5] = incl;
    }
    __syncthreads();
    if (tid < 16) {
        int w = wsum[tid];
        int wi = w;
        #pragma unroll
        for (int d = 1; d < 16; d <<= 1) {
            int t = __shfl_up_sync(0x0000ffffu, wi, d);
            if (tid >= d) wi += t;
        }
        wsum[tid] = wi - w;
    }
    __syncthreads();
    if (tid < LSZ) cnt[LSZ - 1 - tid] = (incl - val) + wsum[tid >> 5];
    __syncthreads();

    int p0 = atomicAdd(&cnt[l0], 1); g_perm[p0] = 2 * tid;
    int p1 = atomicAdd(&cnt[l1], 1); g_perm[p1] = 2 * tid + 1;
}

// ---------------------------------------------------------------------------
// Fused kernel: q/k/v projection + online-softmax attention; K/V of the LIVE
// suffix streamed through a 4-stage cp.async.bulk pipeline. 5 CTAs/SM
// (launch_bounds + 38KB smem) -> 10 bulk streams per SM.
// ---------------------------------------------------------------------------
__global__ __launch_bounds__(256, 5) void attn_kernel(
    const float* __restrict__ x,
    const float* __restrict__ K, const float* __restrict__ V,
    const float* __restrict__ Wq, const float* __restrict__ bq,
    const float* __restrict__ Wk, const float* __restrict__ bk,
    const float* __restrict__ Wv, const float* __restrict__ bv,
    float* __restrict__ out)
{
    __shared__ __align__(1024) float kbuf[NST][TILE][DSZ];   // 16KB
    __shared__ __align__(1024) float vbuf[NST][TILE][DSZ];   // 16KB
    __shared__ __align__(16) float xs[DSZ];
    __shared__ __align__(16) float qs[DSZ];
    __shared__ __align__(16) float ks[DSZ];
    __shared__ __align__(16) float vs[DSZ];
    __shared__ __align__(16) float s_part[8][DSZ];
    __shared__ float red_m[8];
    __shared__ float red_l[8];
    __shared__ __align__(8) unsigned long long mbar[NST];

    int tid  = threadIdx.x;
    int lane = tid & 31;
    int wid  = tid >> 5;
    int b    = g_perm[blockIdx.x];
    int len  = g_len[b];                // 0 .. 511
    int j0   = LSZ - len;
    const float inv_sqrt_d = 0.08838834764831845f;   // 1/sqrt(128)

    size_t base = (size_t)b * LSZ * DSZ;
    const float* Ksuf = K + base + (size_t)j0 * DSZ;    // contiguous len*512B
    const float* Vsuf = V + base + (size_t)j0 * DSZ;
    int ntiles = (len + TILE - 1) / TILE;

    uint32_t mb0 = (uint32_t)__cvta_generic_to_shared(&mbar[0]);
    uint32_t kb0 = (uint32_t)__cvta_generic_to_shared(&kbuf[0][0][0]);
    uint32_t vb0 = (uint32_t)__cvta_generic_to_shared(&vbuf[0][0][0]);

    if (tid == 0) {
        #pragma unroll
        for (int s = 0; s < NST; ++s) mbar_init(mb0 + 8 * s, 1);
        asm volatile("fence.proxy.async.shared::cta;" ::: "memory");
    }
    if (tid < 32) ((float4*)xs)[tid] = ((const float4*)(x + (size_t)b * DSZ))[tid];
    __syncthreads();

    // ---- Prologue: fill the pipeline (overlaps with projection below).
    if (tid == 0) {
        #pragma unroll
        for (int s = 0; s < NST; ++s) {
            if (s < ntiles) {
                int rows = min(TILE, len - s * TILE);
                uint32_t bytes = (uint32_t)rows * DSZ * 4;
                mbar_expect_tx(mb0 + 8 * s, 2 * bytes);
                bulk_g2s(kb0 + s * TILEB, Ksuf + (size_t)s * TILE * DSZ,
                         bytes, mb0 + 8 * s);
                bulk_g2s(vb0 + s * TILEB, Vsuf + (size_t)s * TILE * DSZ,
                         bytes, mb0 + 8 * s);
            }
        }
    }

    // ---- Projection: q[d] = dot(Wq[d,:], x) + bq[d] (same for k,v).
    {
        float4 xv = ((const float4*)xs)[lane];
        #pragma unroll
        for (int mm = 0; mm < 3; ++mm) {
            const float* W    = (mm == 0) ? Wq : ((mm == 1) ? Wk : Wv);
            const float* bias = (mm == 0) ? bq : ((mm == 1) ? bk : bv);
            float* dst        = (mm == 0) ? qs : ((mm == 1) ? ks : vs);
            #pragma unroll
            for (int j = 0; j < 4; ++j) {
                int d0 = wid + 32 * j;
                float4 w0 = ((const float4*)(W + (d0     ) * DSZ))[lane];
                float4 w1 = ((const float4*)(W + (d0 +  8) * DSZ))[lane];
                float4 w2 = ((const float4*)(W + (d0 + 16) * DSZ))[lane];
                float4 w3 = ((const float4*)(W + (d0 + 24) * DSZ))[lane];
                float p0 = dot128(w0, xv);
                float p1 = dot128(w1, xv);
                float p2 = dot128(w2, xv);
                float p3 = dot128(w3, xv);
                WARP_RED_SUM4(p0, p1, p2, p3);
                if (lane == 0) {
                    dst[d0]      = p0 + bias[d0];
                    dst[d0 +  8] = p1 + bias[d0 + 8];
                    dst[d0 + 16] = p2 + bias[d0 + 16];
                    dst[d0 + 24] = p3 + bias[d0 + 24];
                }
            }
        }
    }
    __syncthreads();

    // ---- Online-softmax stream over pipeline tiles. One row per warp per
    // tile -> perfectly balanced per-tile barrier.
    float4 qv = ((const float4*)qs)[lane];
    float  m  = -3.4e38f;
    float  l  = 0.0f;
    float4 o  = make_float4(0.f, 0.f, 0.f, 0.f);

    if (wid == (len & 7)) {              // new pushed entry (order irrelevant)
        float4 kn = ((const float4*)ks)[lane];
        float4 vn = ((const float4*)vs)[lane];
        float p = dot128(kn, qv);
        WARP_RED_SUM(p);
        p *= inv_sqrt_d;
        m = p; l = 1.0f;
        o = vn;
    }

    int s = 0, phase = 0;                // stage index + parity, kept in regs
    for (int t = 0; t < ntiles; ++t) {
        mbar_wait(mb0 + 8 * s, phase);
        int rows = len - t * TILE;       // >= 1; may exceed TILE (clamped use)
        if (wid < rows) {
            float4 k0 = *(const float4*)&kbuf[s][wid][lane * 4];
            float4 v0 = *(const float4*)&vbuf[s][wid][lane * 4];
            float p0 = dot128(k0, qv);
            WARP_RED_SUM(p0);
            p0 *= inv_sqrt_d;
            ONLINE_UPDATE(p0, v0);
        }
        __syncthreads();                 // everyone done reading stage s
        int tn = t + NST;
        if (tid == 0 && tn < ntiles) {   // refill stage s with tile tn
            int rows2 = min(TILE, len - tn * TILE);
            uint32_t bytes = (uint32_t)rows2 * DSZ * 4;
            mbar_expect_tx(mb0 + 8 * s, 2 * bytes);
            bulk_g2s(kb0 + s * TILEB, Ksuf + (size_t)tn * TILE * DSZ,
                     bytes, mb0 + 8 * s);
            bulk_g2s(vb0 + s * TILEB, Vsuf + (size_t)tn * TILE * DSZ,
                     bytes, mb0 + 8 * s);
        }
        if (++s == NST) { s = 0; phase ^= 1; }
    }

    // ---- Merge the 8 per-warp (m, l, o) triples.
    if (lane == 0) red_m[wid] = m;
    __syncthreads();
    float M = red_m[0];
    #pragma unroll
    for (int w = 1; w < 8; ++w) M = fmaxf(M, red_m[w]);
    float f = __expf(m - M);             // 0 for warps that saw no rows
    if (lane == 0) red_l[wid] = l * f;
    o.x *= f; o.y *= f; o.z *= f; o.w *= f;
    ((float4*)&s_part[wid][0])[lane] = o;
    __syncthreads();

    if (tid < DSZ) {
        float L = red_l[0];
        #pragma unroll
        for (int w = 1; w < 8; ++w) L += red_l[w];
        float sm = 0.0f;
        #pragma unroll
        for (int w = 0; w < 8; ++w) sm += s_part[w][tid];
        out[(size_t)b * DSZ + tid] = sm / L;
    }
}

// ---------------------------------------------------------------------------
extern "C" void kernel_launch(void* const* d_in, const int* in_sizes, int n_in,
                              void* d_out, int out_size) {
    const float* inputs      = (const float*)d_in[0];
    const float* prev_keys   = (const float*)d_in[1];
    const float* prev_values = (const float*)d_in[2];
    const float* Wq          = (const float*)d_in[3];
    const float* bq          = (const float*)d_in[4];
    const float* Wk          = (const float*)d_in[5];
    const float* bk          = (const float*)d_in[6];
    const float* Wv          = (const float*)d_in[7];
    const float* bv          = (const float*)d_in[8];
    const int*   lengths_raw = (const int*)d_in[9];
    float* out               = (float*)d_out;

    setup_kernel<<<1, 1024>>>(lengths_raw);
    attn_kernel<<<BSZ, 256>>>(inputs, prev_keys, prev_values,
                              Wq, bq, Wk, bk, Wv, bv, out);
}

// round 11
// speedup vs baseline: 1.0329x; 1.0026x over previous
#include <cuda_runtime.h>
#include <cstdint>

#define BSZ 2048
#define LSZ 512
#define DSZ 128
#define TILE 8           // rows per pipeline stage (4KB K + 4KB V)
#define NST  4           // pipeline depth
#define TILEB (TILE * DSZ * 4)

__device__ int g_len[BSZ];     // normalized lengths (dtype auto-detected)
__device__ int g_perm[BSZ];    // batch rows sorted by descending length

#define WARP_RED_SUM(p)                                   \
    p += __shfl_xor_sync(0xffffffffu, p, 16);             \
    p += __shfl_xor_sync(0xffffffffu, p, 8);              \
    p += __shfl_xor_sync(0xffffffffu, p, 4);              \
    p += __shfl_xor_sync(0xffffffffu, p, 2);              \
    p += __shfl_xor_sync(0xffffffffu, p, 1);

#define WARP_RED_SUM2(a, b)                               \
    a += __shfl_xor_sync(0xffffffffu, a, 16);             \
    b += __shfl_xor_sync(0xffffffffu, b, 16);             \
    a += __shfl_xor_sync(0xffffffffu, a, 8);              \
    b += __shfl_xor_sync(0xffffffffu, b, 8);              \
    a += __shfl_xor_sync(0xffffffffu, a, 4);              \
    b += __shfl_xor_sync(0xffffffffu, b, 4);              \
    a += __shfl_xor_sync(0xffffffffu, a, 2);              \
    b += __shfl_xor_sync(0xffffffffu, b, 2);              \
    a += __shfl_xor_sync(0xffffffffu, a, 1);              \
    b += __shfl_xor_sync(0xffffffffu, b, 1);

#define WARP_RED_SUM4(a, b, c, d)                         \
    WARP_RED_SUM2(a, b)                                   \
    WARP_RED_SUM2(c, d)

__device__ __forceinline__ float dot128(float4 a, float4 b) {
    return fmaf(a.x, b.x, fmaf(a.y, b.y, fmaf(a.z, b.z, a.w * b.w)));
}

// Online softmax update of (m, l, o) with score p and value row v.
#define ONLINE_UPDATE(p, v)                               \
    {                                                     \
        float mn = fmaxf(m, p);                           \
        float cc = __expf(m - mn);                        \
        float ee = __expf(p - mn);                        \
        l = fmaf(l, cc, ee);                              \
        o.x = fmaf(o.x, cc, ee * (v).x);                  \
        o.y = fmaf(o.y, cc, ee * (v).y);                  \
        o.z = fmaf(o.z, cc, ee * (v).z);                  \
        o.w = fmaf(o.w, cc, ee * (v).w);                  \
        m = mn;                                           \
    }

// ---- bulk-async (UBLKCP) + mbarrier primitives --------------------------
__device__ __forceinline__ void mbar_init(uint32_t mbar, uint32_t count) {
    asm volatile("mbarrier.init.shared.b64 [%0], %1;" :: "r"(mbar), "r"(count) : "memory");
}
__device__ __forceinline__ void mbar_expect_tx(uint32_t mbar, uint32_t tx) {
    asm volatile("mbarrier.arrive.expect_tx.shared.b64 _, [%0], %1;"
                 :: "r"(mbar), "r"(tx) : "memory");
}
__device__ __forceinline__ void bulk_g2s(uint32_t dst, const void* src,
                                         uint32_t bytes, uint32_t mbar) {
    asm volatile("cp.async.bulk.shared::cta.global.mbarrier::complete_tx::bytes "
                 "[%0], [%1], %2, [%3];"
                 :: "r"(dst), "l"(src), "r"(bytes), "r"(mbar) : "memory");
}
__device__ __forceinline__ void mbar_wait(uint32_t mbar, uint32_t parity) {
    uint32_t done;
    do {
        asm volatile(
            "{\n\t.reg .pred p;\n\t"
            "mbarrier.try_wait.parity.acquire.cta.shared::cta.b64 p, [%1], %2, 0x989680;\n\t"
            "selp.b32 %0, 1, 0, p;\n\t}"
            : "=r"(done) : "r"(mbar), "r"(parity) : "memory");
    } while (!done);
}

// ---------------------------------------------------------------------------
// Setup: (a) normalize `lengths` to int32 with int32/int64 auto-detect
// (int64 values < 512 have all-zero odd int32 words), (b) counting-sort rows
// by DESCENDING length into g_perm. Parallel shfl-based block scan.
// ---------------------------------------------------------------------------
__global__ __launch_bounds__(1024) void setup_kernel(const int* __restrict__ Lraw) {
    __shared__ int cnt[LSZ];
    __shared__ int wsum[16];
    __shared__ int s_any;
    int tid  = threadIdx.x;                 // single block, 1024 threads
    int lane = tid & 31;
    if (tid == 0) s_any = 0;
    if (tid < LSZ) cnt[tid] = 0;
    __syncthreads();
    if (Lraw[2 * tid + 1] != 0) s_any = 1;  // benign race
    __syncthreads();
    int l0, l1;
    if (s_any == 0) {                       // int64 layout
        const long long* L64 = (const long long*)Lraw;
        l0 = (int)L64[2 * tid];
        l1 = (int)L64[2 * tid + 1];
    } else {                                // int32 layout
        l0 = Lraw[2 * tid];
        l1 = Lraw[2 * tid + 1];
    }
    g_len[2 * tid]     = l0;
    g_len[2 * tid + 1] = l1;
    atomicAdd(&cnt[l0], 1);
    atomicAdd(&cnt[l1], 1);
    __syncthreads();

    int val = 0, incl = 0;
    if (tid < LSZ) {                        // descending exclusive scan
        val  = cnt[LSZ - 1 - tid];
        incl = val;
        #pragma unroll
        for (int d = 1; d < 32; d <<= 1) {
            int t = __shfl_up_sync(0xffffffffu, incl, d);
            if (lane >= d) incl += t;
        }
        if (lane == 31) wsum[tid >> 5] = incl;
    }
    __syncthreads();
    if (tid < 16) {
        int w = wsum[tid];
        int wi = w;
        #pragma unroll
        for (int d = 1; d < 16; d <<= 1) {
            int t = __shfl_up_sync(0x0000ffffu, wi, d);
            if (tid >= d) wi += t;
        }
        wsum[tid] = wi - w;
    }
    __syncthreads();
    if (tid < LSZ) cnt[LSZ - 1 - tid] = (incl - val) + wsum[tid >> 5];
    __syncthreads();

    int p0 = atomicAdd(&cnt[l0], 1); g_perm[p0] = 2 * tid;
    int p1 = atomicAdd(&cnt[l1], 1); g_perm[p1] = 2 * tid + 1;
    // No explicit early trigger: implicit completion at kernel end gives the
    // PDL-dependent attn kernel full visibility of g_len/g_perm.
}

// ---------------------------------------------------------------------------
// Fused kernel: q/k/v projection + online-softmax attention; K/V of the LIVE
// suffix streamed through a 4-stage cp.async.bulk pipeline. Launched with
// PDL: the preamble (mbarrier init) overlaps the setup kernel; the grid
// dependency sync gates the first read of g_perm/g_len.
// ---------------------------------------------------------------------------
__global__ __launch_bounds__(256, 5) void attn_kernel(
    const float* __restrict__ x,
    const float* __restrict__ K, const float* __restrict__ V,
    const float* __restrict__ Wq, const float* __restrict__ bq,
    const float* __restrict__ Wk, const float* __restrict__ bk,
    const float* __restrict__ Wv, const float* __restrict__ bv,
    float* __restrict__ out)
{
    __shared__ __align__(1024) float kbuf[NST][TILE][DSZ];   // 16KB
    __shared__ __align__(1024) float vbuf[NST][TILE][DSZ];   // 16KB
    __shared__ __align__(16) float xs[DSZ];
    __shared__ __align__(16) float qs[DSZ];
    __shared__ __align__(16) float ks[DSZ];
    __shared__ __align__(16) float vs[DSZ];
    __shared__ __align__(16) float s_part[8][DSZ];
    __shared__ float red_m[8];
    __shared__ float red_l[8];
    __shared__ __align__(8) unsigned long long mbar[NST];

    int tid  = threadIdx.x;
    int lane = tid & 31;
    int wid  = tid >> 5;

    uint32_t mb0 = (uint32_t)__cvta_generic_to_shared(&mbar[0]);
    uint32_t kb0 = (uint32_t)__cvta_generic_to_shared(&kbuf[0][0][0]);
    uint32_t vb0 = (uint32_t)__cvta_generic_to_shared(&vbuf[0][0][0]);

    // ---- PDL preamble: runs while setup_kernel is still executing.
    if (tid == 0) {
        #pragma unroll
        for (int s = 0; s < NST; ++s) mbar_init(mb0 + 8 * s, 1);
        asm volatile("fence.proxy.async.shared::cta;" ::: "memory");
    }

    // ---- Wait for setup_kernel's g_len/g_perm.
    cudaGridDependencySynchronize();

    int b    = g_perm[blockIdx.x];
    int len  = g_len[b];                // 0 .. 511
    int j0   = LSZ - len;
    const float inv_sqrt_d = 0.08838834764831845f;   // 1/sqrt(128)

    size_t base = (size_t)b * LSZ * DSZ;
    const float* Ksuf = K + base + (size_t)j0 * DSZ;    // contiguous len*512B
    const float* Vsuf = V + base + (size_t)j0 * DSZ;
    int ntiles = (len + TILE - 1) / TILE;

    if (tid < 32) ((float4*)xs)[tid] = ((const float4*)(x + (size_t)b * DSZ))[tid];
    __syncthreads();

    // ---- Prologue: fill the pipeline (overlaps with projection below).
    if (tid == 0) {
        #pragma unroll
        for (int s = 0; s < NST; ++s) {
            if (s < ntiles) {
                int rows = min(TILE, len - s * TILE);
                uint32_t bytes = (uint32_t)rows * DSZ * 4;
                mbar_expect_tx(mb0 + 8 * s, 2 * bytes);
                bulk_g2s(kb0 + s * TILEB, Ksuf + (size_t)s * TILE * DSZ,
                         bytes, mb0 + 8 * s);
                bulk_g2s(vb0 + s * TILEB, Vsuf + (size_t)s * TILE * DSZ,
                         bytes, mb0 + 8 * s);
            }
        }
    }

    // ---- Projection: q[d] = dot(Wq[d,:], x) + bq[d] (same for k,v).
    {
        float4 xv = ((const float4*)xs)[lane];
        #pragma unroll
        for (int mm = 0; mm < 3; ++mm) {
            const float* W    = (mm == 0) ? Wq : ((mm == 1) ? Wk : Wv);
            const float* bias = (mm == 0) ? bq : ((mm == 1) ? bk : bv);
            float* dst        = (mm == 0) ? qs : ((mm == 1) ? ks : vs);
            #pragma unroll
            for (int j = 0; j < 4; ++j) {
                int d0 = wid + 32 * j;
                float4 w0 = ((const float4*)(W + (d0     ) * DSZ))[lane];
                float4 w1 = ((const float4*)(W + (d0 +  8) * DSZ))[lane];
                float4 w2 = ((const float4*)(W + (d0 + 16) * DSZ))[lane];
                float4 w3 = ((const float4*)(W + (d0 + 24) * DSZ))[lane];
                float p0 = dot128(w0, xv);
                float p1 = dot128(w1, xv);
                float p2 = dot128(w2, xv);
                float p3 = dot128(w3, xv);
                WARP_RED_SUM4(p0, p1, p2, p3);
                if (lane == 0) {
                    dst[d0]      = p0 + bias[d0];
                    dst[d0 +  8] = p1 + bias[d0 + 8];
                    dst[d0 + 16] = p2 + bias[d0 + 16];
                    dst[d0 + 24] = p3 + bias[d0 + 24];
                }
            }
        }
    }
    __syncthreads();

    // ---- Online-softmax stream over pipeline tiles. One row per warp per
    // tile -> perfectly balanced per-tile barrier.
    float4 qv = ((const float4*)qs)[lane];
    float  m  = -3.4e38f;
    float  l  = 0.0f;
    float4 o  = make_float4(0.f, 0.f, 0.f, 0.f);

    if (wid == (len & 7)) {              // new pushed entry (order irrelevant)
        float4 kn = ((const float4*)ks)[lane];
        float4 vn = ((const float4*)vs)[lane];
        float p = dot128(kn, qv);
        WARP_RED_SUM(p);
        p *= inv_sqrt_d;
        m = p; l = 1.0f;
        o = vn;
    }

    int s = 0, phase = 0;                // stage index + parity, kept in regs
    for (int t = 0; t < ntiles; ++t) {
        mbar_wait(mb0 + 8 * s, phase);
        int rows = len - t * TILE;       // >= 1; may exceed TILE (clamped use)
        if (wid < rows) {
            float4 k0 = *(const float4*)&kbuf[s][wid][lane * 4];
            float4 v0 = *(const float4*)&vbuf[s][wid][lane * 4];
            float p0 = dot128(k0, qv);
            WARP_RED_SUM(p0);
            p0 *= inv_sqrt_d;
            ONLINE_UPDATE(p0, v0);
        }
        __syncthreads();                 // everyone done reading stage s
        int tn = t + NST;
        if (tid == 0 && tn < ntiles) {   // refill stage s with tile tn
            int rows2 = min(TILE, len - tn * TILE);
            uint32_t bytes = (uint32_t)rows2 * DSZ * 4;
            mbar_expect_tx(mb0 + 8 * s, 2 * bytes);
            bulk_g2s(kb0 + s * TILEB, Ksuf + (size_t)tn * TILE * DSZ,
                     bytes, mb0 + 8 * s);
            bulk_g2s(vb0 + s * TILEB, Vsuf + (size_t)tn * TILE * DSZ,
                     bytes, mb0 + 8 * s);
        }
        if (++s == NST) { s = 0; phase ^= 1; }
    }

    // ---- Merge the 8 per-warp (m, l, o) triples.
    if (lane == 0) red_m[wid] = m;
    __syncthreads();
    float M = red_m[0];
    #pragma unroll
    for (int w = 1; w < 8; ++w) M = fmaxf(M, red_m[w]);
    float f = __expf(m - M);             // 0 for warps that saw no rows
    if (lane == 0) red_l[wid] = l * f;
    o.x *= f; o.y *= f; o.z *= f; o.w *= f;
    ((float4*)&s_part[wid][0])[lane] = o;
    __syncthreads();

    if (tid < DSZ) {
        float L = red_l[0];
        #pragma unroll
        for (int w = 1; w < 8; ++w) L += red_l[w];
        float sm = 0.0f;
        #pragma unroll
        for (int w = 0; w < 8; ++w) sm += s_part[w][tid];
        out[(size_t)b * DSZ + tid] = sm / L;
    }
}

// ---------------------------------------------------------------------------
extern "C" void kernel_launch(void* const* d_in, const int* in_sizes, int n_in,
                              void* d_out, int out_size) {
    const float* inputs      = (const float*)d_in[0];
    const float* prev_keys   = (const float*)d_in[1];
    const float* prev_values = (const float*)d_in[2];
    const float* Wq          = (const float*)d_in[3];
    const float* bq          = (const float*)d_in[4];
    const float* Wk          = (const float*)d_in[5];
    const float* bk          = (const float*)d_in[6];
    const float* Wv          = (const float*)d_in[7];
    const float* bv          = (const float*)d_in[8];
    const int*   lengths_raw = (const int*)d_in[9];
    float* out               = (float*)d_out;

    setup_kernel<<<1, 1024>>>(lengths_raw);

    // Launch attn with Programmatic Dependent Launch so its preamble overlaps
    // setup_kernel; the in-kernel cudaGridDependencySynchronize gates g_perm.
    cudaLaunchConfig_t cfg = {};
    cfg.gridDim  = dim3(BSZ, 1, 1);
    cfg.blockDim = dim3(256, 1, 1);
    cfg.dynamicSmemBytes = 0;
    cfg.stream = 0;                      // legacy default stream (same as <<<>>>)
    cudaLaunchAttribute attrs[1];
    attrs[0].id = cudaLaunchAttributeProgrammaticStreamSerialization;
    attrs[0].val.programmaticStreamSerializationAllowed = 1;
    cfg.attrs = attrs;
    cfg.numAttrs = 1;
    cudaLaunchKernelEx(&cfg, attn_kernel, inputs, prev_keys, prev_values,
                       Wq, bq, Wk, bk, Wv, bv, out);
}